// round 8
// baseline (speedup 1.0000x reference)
#include <cuda_runtime.h>
#include <cstdint>

#define T_DIM 256
#define D_DIM 44
#define H_DIM 8
#define NPATHS 8192
#define NGROUPS 1024
#define RING 4

// scratch
__device__ float g_hlast[NPATHS * H_DIM];
__device__ int   g_order[NPATHS];

__device__ __forceinline__ float fast_ex2(float x) {
    float r; asm("ex2.approx.f32 %0, %1;" : "=f"(r) : "f"(x)); return r;
}
__device__ __forceinline__ float fast_rcp(float x) {
    float r; asm("rcp.approx.f32 %0, %1;" : "=f"(r) : "f"(x)); return r;
}

typedef unsigned long long ull;
union F2U { ull u; float2 f; };

__device__ __forceinline__ ull pack2(float a, float b) {
    F2U t; t.f.x = a; t.f.y = b; return t.u;
}
__device__ __forceinline__ void ffma2(ull& d, ull a, ull b) {
    asm("fma.rn.f32x2 %0, %1, %2, %0;" : "+l"(d) : "l"(a), "l"(b));
}
__device__ __forceinline__ ull fma2v(ull a, ull b, ull c) {
    ull r; asm("fma.rn.f32x2 %0, %1, %2, %3;" : "=l"(r) : "l"(a), "l"(b), "l"(c)); return r;
}
__device__ __forceinline__ ull mul2(ull a, ull b) {
    ull r; asm("mul.rn.f32x2 %0, %1, %2;" : "=l"(r) : "l"(a), "l"(b)); return r;
}
__device__ __forceinline__ ull add2(ull a, ull b) {
    ull r; asm("add.rn.f32x2 %0, %1, %2;" : "=l"(r) : "l"(a), "l"(b)); return r;
}
__device__ __forceinline__ ull ex2_2(ull v) {
    F2U t; t.u = v; t.f.x = fast_ex2(t.f.x); t.f.y = fast_ex2(t.f.y); return t.u;
}
__device__ __forceinline__ ull rcp_2(ull v) {
    F2U t; t.u = v; t.f.x = fast_rcp(t.f.x); t.f.y = fast_rcp(t.f.y); return t.u;
}

__device__ __forceinline__ unsigned int smem_u32(const void* p) {
    return (unsigned int)__cvta_generic_to_shared(p);
}
__device__ __forceinline__ void cp16_pred(unsigned int dst, const void* src, bool pred) {
    asm volatile(
        "{ .reg .pred q; setp.ne.u32 q, %2, 0;"
        " @q cp.async.ca.shared.global [%0], [%1], 16; }"
        :: "r"(dst), "l"(src), "r"((int)pred));
}
#define CP_COMMIT() asm volatile("cp.async.commit_group;" ::: "memory")
#define CP_WAIT2()  asm volatile("cp.async.wait_group 2;" ::: "memory")

// ─────────────────────────────────────────────────────────────────────────────
// Counting sort by last_idx DESCENDING (parallel scan).
// ─────────────────────────────────────────────────────────────────────────────
__global__ void __launch_bounds__(1024)
sort_kernel(const int* __restrict__ last_idx)
{
    __shared__ int cnt[256];
    __shared__ int soff[256];
    __shared__ int wsum[8];
    __shared__ int wpre[8];
    const int tid = threadIdx.x;

    if (tid < 256) cnt[tid] = 0;
    __syncthreads();
    for (int i = tid; i < NPATHS; i += 1024) atomicAdd(&cnt[last_idx[i]], 1);
    __syncthreads();

    int v = 0;
    if (tid < 256) {
        const int r = tid;
        v = cnt[255 - r];
        #pragma unroll
        for (int d = 1; d < 32; d <<= 1) {
            int n = __shfl_up_sync(0xffffffffu, v, d);
            if ((r & 31) >= d) v += n;
        }
        if ((r & 31) == 31) wsum[r >> 5] = v;
    }
    __syncthreads();
    if (tid == 0) {
        int run = 0;
        #pragma unroll
        for (int w = 0; w < 8; w++) { wpre[w] = run; run += wsum[w]; }
    }
    __syncthreads();
    if (tid < 256) {
        const int r = tid;
        soff[255 - r] = v - cnt[255 - r] + wpre[r >> 5];
    }
    __syncthreads();
    if (tid < 256) cnt[tid] = 0;
    __syncthreads();

    for (int i = tid; i < NPATHS; i += 1024) {
        const int L = last_idx[i];
        const int pos = soff[L] + atomicAdd(&cnt[L], 1);
        g_order[pos] = i;
    }
}

// ─────────────────────────────────────────────────────────────────────────────
// LSTM: 1 warp/block, two length-matched paths, A/B packed in f32x2 lanes.
// W_ih in smem (own-column LDS.64, shared by both paths); x via cp.async ring.
// No state freeze: h stored exactly at t == last; garbage runs harmlessly after.
// ─────────────────────────────────────────────────────────────────────────────
__global__ void __launch_bounds__(32, 24)
lstm_kernel(const float* __restrict__ x,
            const float* __restrict__ W_ih,
            const float* __restrict__ W_hh,
            const float* __restrict__ b_ih,
            const float* __restrict__ b_hh,
            const int* __restrict__ last_idx)
{
    __shared__ float4 sx[RING][2][11];   // x ring: [stage][side][11 float4]
    __shared__ ull    swT[22][32];       // W_ih packed pairs, [k2][lane]

    const int lane = threadIdx.x;
    const int pA = g_order[2 * blockIdx.x];
    const int pB = g_order[2 * blockIdx.x + 1];

    // W_ih row -> own smem column (packed over k); read back lane-local only.
    {
        const float2* wr = (const float2*)(W_ih + lane * 44);
        #pragma unroll
        for (int k2 = 0; k2 < 22; k2++) {
            float2 v = wr[k2];
            swT[k2][lane] = pack2(v.x, v.y);
        }
    }
    // W_hh row, duplicated per half for packed A/B math
    ull whh2[8];
    {
        const float4* wr = (const float4*)(W_hh + lane * 8);
        float4 v0 = wr[0], v1 = wr[1];
        whh2[0]=pack2(v0.x,v0.x); whh2[1]=pack2(v0.y,v0.y);
        whh2[2]=pack2(v0.z,v0.z); whh2[3]=pack2(v0.w,v0.w);
        whh2[4]=pack2(v1.x,v1.x); whh2[5]=pack2(v1.y,v1.y);
        whh2[6]=pack2(v1.z,v1.z); whh2[7]=pack2(v1.w,v1.w);
    }
    const float bias = b_ih[lane] + b_hh[lane];
    const ull biasPk = pack2(bias, 0.0f);

    // branchless activation (lanes 16-23 = g gate -> tanh form)
    const bool isg = (lane >= 16) && (lane < 24);
    const float m_s  = isg ?  2.8853900817779268f : -1.4426950408889634f;
    const float al_s = isg ?  1.0f : 0.0f;
    const float be_s = isg ? -2.0f : 1.0f;
    const ull m2   = pack2(m_s, m_s);
    const ull al2  = pack2(al_s, al_s);
    const ull be2  = pack2(be_s, be_s);
    const ull one2 = pack2(1.0f, 1.0f);
    const ull K2   = pack2(2.8853900817779268f, 2.8853900817779268f);
    const ull neg2 = pack2(-2.0f, -2.0f);

    const int lastA = last_idx[pA];
    const int lastB = last_idx[pB];
    const int tmax  = max(lastA, lastB);
    const int jl    = lane & 7;

    const float4* xrA = (const float4*)(x + (size_t)pA * T_DIM * D_DIM);
    const float4* xrB = (const float4*)(x + (size_t)pB * T_DIM * D_DIM);

    // loaders: lanes 0-10 -> side A, lanes 16-26 -> side B
    const int  side   = lane >> 4;
    const int  slot   = lane & 15;
    const bool ldr    = slot < 11;
    const float4* myx = side ? xrB : xrA;
    const int  mylast = side ? lastB : lastA;
    const unsigned int sbase  = smem_u32(&sx[0][0][0]);
    const unsigned int mydst0 = (unsigned int)((side * 11 + slot) * 16);

    // prologue: prefetch stages 0..3
    #pragma unroll
    for (int p = 0; p < RING; p++) {
        cp16_pred(sbase + (unsigned int)(p * 352) + mydst0,
                  myx + (size_t)p * 11 + slot,
                  ldr && (p <= mylast));
        CP_COMMIT();
    }

    ull hAB[8];
    #pragma unroll
    for (int j = 0; j < 8; j++) hAB[j] = 0ull;
    ull c2 = 0ull;

    const bool wrA = (lane < 8);
    const bool wrB = (lane >= 8) && (lane < 16);
    float* outA = g_hlast + pA * H_DIM + lane;
    float* outB = g_hlast + pB * H_DIM + (lane - 8);

    // initial xd(0)
    ull xd2;
    CP_WAIT2();
    __syncwarp();
    {
        const ulonglong2* xsA = (const ulonglong2*)&sx[0][0][0];
        const ulonglong2* xsB = (const ulonglong2*)&sx[0][1][0];
        ull a0A = biasPk, a1A = 0ull, a0B = biasPk, a1B = 0ull;
        #pragma unroll
        for (int k = 0; k < 11; k++) {
            const ull w0 = swT[2*k][lane];
            const ull w1 = swT[2*k+1][lane];
            ulonglong2 xvA = xsA[k];
            ulonglong2 xvB = xsB[k];
            ffma2(a0A, w0, xvA.x);
            ffma2(a1A, w1, xvA.y);
            ffma2(a0B, w0, xvB.x);
            ffma2(a1B, w1, xvB.y);
        }
        F2U sA; sA.u = add2(a0A, a1A);
        F2U sB; sB.u = add2(a0B, a1B);
        xd2 = pack2(sA.f.x + sA.f.y, sB.f.x + sB.f.y);
    }

    for (int t = 0; t <= tmax; t++) {
        CP_WAIT2();
        __syncwarp();

        // ── independent: dot(t+1) for both paths ──
        const int stg1 = (t + 1) & (RING - 1);
        const ulonglong2* xsA = (const ulonglong2*)&sx[stg1][0][0];
        const ulonglong2* xsB = (const ulonglong2*)&sx[stg1][1][0];
        ull a0A = biasPk, a1A = 0ull, a0B = biasPk, a1B = 0ull;
        #pragma unroll
        for (int k = 0; k < 11; k++) {
            const ull w0 = swT[2*k][lane];
            const ull w1 = swT[2*k+1][lane];
            ulonglong2 xvA = xsA[k];
            ulonglong2 xvB = xsB[k];
            ffma2(a0A, w0, xvA.x);
            ffma2(a1A, w1, xvA.y);
            ffma2(a0B, w0, xvB.x);
            ffma2(a1B, w1, xvB.y);
        }

        // prefetch stage t+4
        const int tp = t + RING;
        cp16_pred(sbase + (unsigned int)((tp & (RING - 1)) * 352) + mydst0,
                  myx + (size_t)tp * 11 + slot,
                  ldr && (tp <= mylast));
        CP_COMMIT();

        // ── chain(t), fully packed {A,B} ──
        ull acc2 = xd2;
        ffma2(acc2, whh2[0], hAB[0]);
        ffma2(acc2, whh2[1], hAB[1]);
        ffma2(acc2, whh2[2], hAB[2]);
        ffma2(acc2, whh2[3], hAB[3]);
        ffma2(acc2, whh2[4], hAB[4]);
        ffma2(acc2, whh2[5], hAB[5]);
        ffma2(acc2, whh2[6], hAB[6]);
        ffma2(acc2, whh2[7], hAB[7]);

        // a2 = al + be * rcp(1 + ex2(m * acc))
        const ull u2 = rcp_2(add2(one2, ex2_2(mul2(m2, acc2))));
        const ull a2 = fma2v(be2, u2, al2);

        // gather i/f/g/o (packed 64-bit shfl)
        const ull iv2 = __shfl_sync(0xffffffffu, a2, jl);
        const ull fv2 = __shfl_sync(0xffffffffu, a2, jl + 8);
        const ull gv2 = __shfl_sync(0xffffffffu, a2, jl + 16);
        const ull ov2 = __shfl_sync(0xffffffffu, a2, jl + 24);

        // c' = f*c + i*g ; h = o * tanh(c')
        c2 = fma2v(fv2, c2, mul2(iv2, gv2));
        const ull th2 = fma2v(neg2, rcp_2(add2(one2, ex2_2(mul2(K2, c2)))), one2);
        const ull hl2 = mul2(ov2, th2);

        // store h exactly at this path's last step
        {
            F2U h; h.u = hl2;
            if (wrA && (t == lastA)) *outA = h.f.x;
            if (wrB && (t == lastB)) *outB = h.f.y;
        }

        // broadcast h (packed): lane j holds h[j] for both paths
        hAB[0] = __shfl_sync(0xffffffffu, hl2, 0);
        hAB[1] = __shfl_sync(0xffffffffu, hl2, 1);
        hAB[2] = __shfl_sync(0xffffffffu, hl2, 2);
        hAB[3] = __shfl_sync(0xffffffffu, hl2, 3);
        hAB[4] = __shfl_sync(0xffffffffu, hl2, 4);
        hAB[5] = __shfl_sync(0xffffffffu, hl2, 5);
        hAB[6] = __shfl_sync(0xffffffffu, hl2, 6);
        hAB[7] = __shfl_sync(0xffffffffu, hl2, 7);

        // collapse next xd (off the critical chain)
        {
            F2U sA; sA.u = add2(a0A, a1A);
            F2U sB; sB.u = add2(a0B, a1B);
            xd2 = pack2(sA.f.x + sA.f.y, sB.f.x + sB.f.y);
        }
    }
}

// ─────────────────────────────────────────────────────────────────────────────
// Finalize: per-path fc dot -> smem; counts + block scan -> segment sums;
// shfl softmax. One 1024-thread block.
// ─────────────────────────────────────────────────────────────────────────────
__global__ void __launch_bounds__(NGROUPS)
finalize_kernel(const int* __restrict__ group_ids,
                const float* __restrict__ fc_W,
                const float* __restrict__ fc_b,
                float* __restrict__ out)
{
    __shared__ float sdot[NPATHS];
    __shared__ int   scnt[NGROUPS];
    __shared__ int   sstart[NGROUPS];
    __shared__ int   wsum[32];
    __shared__ float warpred[32];
    __shared__ float bc;

    const int tid = threadIdx.x;
    const int wid = tid >> 5;
    const int lid = tid & 31;

    float w[8];
    #pragma unroll
    for (int j = 0; j < 8; j++) w[j] = fc_W[j];

    scnt[tid] = 0;
    __syncthreads();

    #pragma unroll
    for (int r = 0; r < NPATHS / NGROUPS; r++) {
        const int i = tid + r * NGROUPS;
        const float4* hp = (const float4*)(g_hlast + i * H_DIM);
        float4 h0 = hp[0], h1 = hp[1];
        float s = h0.x * w[0];
        s = fmaf(h0.y, w[1], s);
        s = fmaf(h0.z, w[2], s);
        s = fmaf(h0.w, w[3], s);
        s = fmaf(h1.x, w[4], s);
        s = fmaf(h1.y, w[5], s);
        s = fmaf(h1.z, w[6], s);
        s = fmaf(h1.w, w[7], s);
        sdot[i] = s;
        atomicAdd(&scnt[group_ids[i]], 1);
    }
    __syncthreads();

    const int myc = scnt[tid];
    int inc = myc;
    #pragma unroll
    for (int d = 1; d < 32; d <<= 1) {
        int n = __shfl_up_sync(0xffffffffu, inc, d);
        if (lid >= d) inc += n;
    }
    if (lid == 31) wsum[wid] = inc;
    __syncthreads();
    if (wid == 0) {
        int v = wsum[lid];
        int iv = v;
        #pragma unroll
        for (int d = 1; d < 32; d <<= 1) {
            int n = __shfl_up_sync(0xffffffffu, iv, d);
            if (lid >= d) iv += n;
        }
        wsum[lid] = iv - v;
    }
    __syncthreads();
    sstart[tid] = inc - myc + wsum[wid];
    __syncthreads();

    float logit = fc_b[0];
    {
        const int s = sstart[tid];
        const int e = s + myc;
        for (int i = s; i < e; i++) logit += sdot[i];
    }

    float m = logit;
    #pragma unroll
    for (int off = 16; off > 0; off >>= 1) m = fmaxf(m, __shfl_xor_sync(0xffffffffu, m, off));
    if (lid == 0) warpred[wid] = m;
    __syncthreads();
    if (wid == 0) {
        float v = warpred[lid];
        #pragma unroll
        for (int off = 16; off > 0; off >>= 1) v = fmaxf(v, __shfl_xor_sync(0xffffffffu, v, off));
        if (lid == 0) bc = v;
    }
    __syncthreads();
    const float mx = bc;

    const float e = __expf(logit - mx);

    float s = e;
    #pragma unroll
    for (int off = 16; off > 0; off >>= 1) s += __shfl_xor_sync(0xffffffffu, s, off);
    __syncthreads();
    if (lid == 0) warpred[wid] = s;
    __syncthreads();
    if (wid == 0) {
        float v = warpred[lid];
        #pragma unroll
        for (int off = 16; off > 0; off >>= 1) v += __shfl_xor_sync(0xffffffffu, v, off);
        if (lid == 0) bc = v;
    }
    __syncthreads();

    out[tid] = e * fast_rcp(bc);
}

extern "C" void kernel_launch(void* const* d_in, const int* in_sizes, int n_in,
                              void* d_out, int out_size)
{
    const float* x      = (const float*)d_in[0];
    const float* W_ih   = (const float*)d_in[1];
    const float* W_hh   = (const float*)d_in[2];
    const float* b_ih   = (const float*)d_in[3];
    const float* b_hh   = (const float*)d_in[4];
    const float* fc_W   = (const float*)d_in[5];
    const float* fc_b   = (const float*)d_in[6];
    const int*   last_i = (const int*)d_in[7];
    const int*   gids   = (const int*)d_in[8];
    float*       out    = (float*)d_out;

    sort_kernel<<<1, 1024>>>(last_i);
    lstm_kernel<<<NPATHS / 2, 32>>>(x, W_ih, W_hh, b_ih, b_hh, last_i);
    finalize_kernel<<<1, NGROUPS>>>(gids, fc_W, fc_b, out);
}

// round 9
// speedup vs baseline: 1.5933x; 1.5933x over previous
#include <cuda_runtime.h>
#include <cstdint>

#define T_DIM 256
#define D_DIM 44
#define H_DIM 8
#define NPATHS 8192
#define NGROUPS 1024
#define RING 4

// scratch
__device__ float g_hlast[NPATHS * H_DIM];
__device__ int   g_order[NPATHS];

__device__ __forceinline__ float fast_ex2(float x) {
    float r; asm("ex2.approx.f32 %0, %1;" : "=f"(r) : "f"(x)); return r;
}
__device__ __forceinline__ float fast_rcp(float x) {
    float r; asm("rcp.approx.f32 %0, %1;" : "=f"(r) : "f"(x)); return r;
}

typedef unsigned long long ull;
union F2U { ull u; float2 f; };

__device__ __forceinline__ ull pack2(float a, float b) {
    F2U t; t.f.x = a; t.f.y = b; return t.u;
}
__device__ __forceinline__ void ffma2(ull& d, ull a, ull b) {
    asm("fma.rn.f32x2 %0, %1, %2, %0;" : "+l"(d) : "l"(a), "l"(b));
}
__device__ __forceinline__ ull fma2v(ull a, ull b, ull c) {
    ull r; asm("fma.rn.f32x2 %0, %1, %2, %3;" : "=l"(r) : "l"(a), "l"(b), "l"(c)); return r;
}
__device__ __forceinline__ ull mul2(ull a, ull b) {
    ull r; asm("mul.rn.f32x2 %0, %1, %2;" : "=l"(r) : "l"(a), "l"(b)); return r;
}
__device__ __forceinline__ ull add2(ull a, ull b) {
    ull r; asm("add.rn.f32x2 %0, %1, %2;" : "=l"(r) : "l"(a), "l"(b)); return r;
}
__device__ __forceinline__ ull ex2_2(ull v) {
    F2U t; t.u = v; t.f.x = fast_ex2(t.f.x); t.f.y = fast_ex2(t.f.y); return t.u;
}
__device__ __forceinline__ ull rcp_2(ull v) {
    F2U t; t.u = v; t.f.x = fast_rcp(t.f.x); t.f.y = fast_rcp(t.f.y); return t.u;
}

__device__ __forceinline__ unsigned int smem_u32(const void* p) {
    return (unsigned int)__cvta_generic_to_shared(p);
}
__device__ __forceinline__ void cp16_pred(unsigned int dst, const void* src, bool pred) {
    asm volatile(
        "{ .reg .pred q; setp.ne.u32 q, %2, 0;"
        " @q cp.async.ca.shared.global [%0], [%1], 16; }"
        :: "r"(dst), "l"(src), "r"((int)pred));
}
#define CP_COMMIT() asm volatile("cp.async.commit_group;" ::: "memory")
#define CP_WAIT2()  asm volatile("cp.async.wait_group 2;" ::: "memory")

// ─────────────────────────────────────────────────────────────────────────────
// Counting sort by last_idx DESCENDING (parallel scan, int4-vectorized).
// ─────────────────────────────────────────────────────────────────────────────
__global__ void __launch_bounds__(1024)
sort_kernel(const int* __restrict__ last_idx)
{
    __shared__ int cnt[256];
    __shared__ int soff[256];
    __shared__ int wsum[8];
    __shared__ int wpre[8];
    const int tid = threadIdx.x;

    if (tid < 256) cnt[tid] = 0;
    __syncthreads();
    const int4* li4 = (const int4*)last_idx;
    #pragma unroll
    for (int i = tid; i < NPATHS / 4; i += 1024) {
        int4 v = li4[i];
        atomicAdd(&cnt[v.x], 1);
        atomicAdd(&cnt[v.y], 1);
        atomicAdd(&cnt[v.z], 1);
        atomicAdd(&cnt[v.w], 1);
    }
    __syncthreads();

    int v = 0;
    if (tid < 256) {
        const int r = tid;
        v = cnt[255 - r];
        #pragma unroll
        for (int d = 1; d < 32; d <<= 1) {
            int n = __shfl_up_sync(0xffffffffu, v, d);
            if ((r & 31) >= d) v += n;
        }
        if ((r & 31) == 31) wsum[r >> 5] = v;
    }
    __syncthreads();
    if (tid == 0) {
        int run = 0;
        #pragma unroll
        for (int w = 0; w < 8; w++) { wpre[w] = run; run += wsum[w]; }
    }
    __syncthreads();
    if (tid < 256) {
        const int r = tid;
        soff[255 - r] = v - cnt[255 - r] + wpre[r >> 5];
    }
    __syncthreads();
    if (tid < 256) cnt[tid] = 0;
    __syncthreads();

    #pragma unroll
    for (int i = tid; i < NPATHS / 4; i += 1024) {
        int4 L = li4[i];
        const int base = i * 4;
        g_order[soff[L.x] + atomicAdd(&cnt[L.x], 1)] = base + 0;
        g_order[soff[L.y] + atomicAdd(&cnt[L.y], 1)] = base + 1;
        g_order[soff[L.z] + atomicAdd(&cnt[L.z], 1)] = base + 2;
        g_order[soff[L.w] + atomicAdd(&cnt[L.w], 1)] = base + 3;
    }
}

// ─────────────────────────────────────────────────────────────────────────────
// LSTM: 1 warp/block, two length-matched paths packed {A,B} in f32x2.
// Weights in REGISTERS (lane-varying smem was the R8 mistake). h exchanged via
// one STS.64 + 4 warp-uniform LDS.128, ordered by the existing per-iter sync.
// ─────────────────────────────────────────────────────────────────────────────
__global__ void __launch_bounds__(32, 18)
lstm_kernel(const float* __restrict__ x,
            const float* __restrict__ W_ih,
            const float* __restrict__ W_hh,
            const float* __restrict__ b_ih,
            const float* __restrict__ b_hh,
            const int* __restrict__ last_idx)
{
    __shared__ float4 sx[RING][2][11];        // x ring: [stage][side][11 float4]
    __shared__ __align__(16) ull shh[8];      // h packed {hA[j], hB[j]}

    const int lane = threadIdx.x;
    const int pA = g_order[2 * blockIdx.x];
    const int pB = g_order[2 * blockIdx.x + 1];

    // packed W_ih row for this lane's gate (REGISTERS)
    ull wihP[22];
    {
        const ulonglong2* wr = (const ulonglong2*)(W_ih + lane * 44);
        #pragma unroll
        for (int k = 0; k < 11; k++) {
            ulonglong2 v = wr[k];
            wihP[2*k]   = v.x;
            wihP[2*k+1] = v.y;
        }
    }
    // W_hh row, dup-packed for {A,B} math
    ull whh2[8];
    {
        const float4* wr = (const float4*)(W_hh + lane * 8);
        float4 v0 = wr[0], v1 = wr[1];
        whh2[0]=pack2(v0.x,v0.x); whh2[1]=pack2(v0.y,v0.y);
        whh2[2]=pack2(v0.z,v0.z); whh2[3]=pack2(v0.w,v0.w);
        whh2[4]=pack2(v1.x,v1.x); whh2[5]=pack2(v1.y,v1.y);
        whh2[6]=pack2(v1.z,v1.z); whh2[7]=pack2(v1.w,v1.w);
    }
    const float bias = b_ih[lane] + b_hh[lane];
    const ull biasPk = pack2(bias, 0.0f);

    // branchless activation (lanes 16-23 = g gate -> tanh form)
    const bool isg = (lane >= 16) && (lane < 24);
    const float m_s  = isg ?  2.8853900817779268f : -1.4426950408889634f;
    const float al_s = isg ?  1.0f : 0.0f;
    const float be_s = isg ? -2.0f : 1.0f;
    const ull m2   = pack2(m_s, m_s);
    const ull al2  = pack2(al_s, al_s);
    const ull be2  = pack2(be_s, be_s);
    const ull one2 = pack2(1.0f, 1.0f);
    const ull K2   = pack2(2.8853900817779268f, 2.8853900817779268f);
    const ull neg2 = pack2(-2.0f, -2.0f);

    const int lastA = last_idx[pA];
    const int lastB = last_idx[pB];
    const int tmax  = max(lastA, lastB);
    const int jl    = lane & 7;

    const float4* xrA = (const float4*)(x + (size_t)pA * T_DIM * D_DIM);
    const float4* xrB = (const float4*)(x + (size_t)pB * T_DIM * D_DIM);

    // loaders: lanes 0-10 -> side A, lanes 16-26 -> side B
    const int  side   = lane >> 4;
    const int  slot   = lane & 15;
    const bool ldr    = slot < 11;
    const float4* myx = side ? xrB : xrA;
    const int  mylast = side ? lastB : lastA;
    const unsigned int sbase  = smem_u32(&sx[0][0][0]);
    const unsigned int mydst0 = (unsigned int)((side * 11 + slot) * 16);

    // init h buffer
    if (lane < 8) shh[lane] = 0ull;

    // prologue: prefetch stages 0..3
    #pragma unroll
    for (int p = 0; p < RING; p++) {
        cp16_pred(sbase + (unsigned int)(p * 352) + mydst0,
                  myx + (size_t)p * 11 + slot,
                  ldr && (p <= mylast));
        CP_COMMIT();
    }

    ull c2 = 0ull;
    float* outA = g_hlast + pA * H_DIM + lane;        // valid when lane < 8
    float* outB = g_hlast + pB * H_DIM + lane;

    // initial xd(0)
    ull xd2;
    CP_WAIT2();
    __syncwarp();
    {
        const ulonglong2* xsA = (const ulonglong2*)&sx[0][0][0];
        const ulonglong2* xsB = (const ulonglong2*)&sx[0][1][0];
        ull a0A = biasPk, a1A = 0ull, a0B = biasPk, a1B = 0ull;
        #pragma unroll
        for (int k = 0; k < 11; k++) {
            ulonglong2 xvA = xsA[k];
            ulonglong2 xvB = xsB[k];
            ffma2(a0A, wihP[2*k],   xvA.x);
            ffma2(a1A, wihP[2*k+1], xvA.y);
            ffma2(a0B, wihP[2*k],   xvB.x);
            ffma2(a1B, wihP[2*k+1], xvB.y);
        }
        F2U sA; sA.u = add2(a0A, a1A);
        F2U sB; sB.u = add2(a0B, a1B);
        xd2 = pack2(sA.f.x + sA.f.y, sB.f.x + sB.f.y);
    }

    for (int t = 0; t <= tmax; t++) {
        CP_WAIT2();
        __syncwarp();   // x(t+1) visible warp-wide; also orders shh STS(t-1) -> LDS

        // load packed h(t-1): 4 warp-uniform LDS.128
        const ulonglong2* hp = (const ulonglong2*)shh;
        const ulonglong2 h01 = hp[0];
        const ulonglong2 h23 = hp[1];
        const ulonglong2 h45 = hp[2];
        const ulonglong2 h67 = hp[3];

        // ── independent: dot(t+1) for both paths (fills chain stall shadows) ──
        const int stg1 = (t + 1) & (RING - 1);
        const ulonglong2* xsA = (const ulonglong2*)&sx[stg1][0][0];
        const ulonglong2* xsB = (const ulonglong2*)&sx[stg1][1][0];
        ull a0A = biasPk, a1A = 0ull, a0B = biasPk, a1B = 0ull;
        #pragma unroll
        for (int k = 0; k < 11; k++) {
            ulonglong2 xvA = xsA[k];
            ulonglong2 xvB = xsB[k];
            ffma2(a0A, wihP[2*k],   xvA.x);
            ffma2(a1A, wihP[2*k+1], xvA.y);
            ffma2(a0B, wihP[2*k],   xvB.x);
            ffma2(a1B, wihP[2*k+1], xvB.y);
        }

        // prefetch stage t+4
        const int tp = t + RING;
        cp16_pred(sbase + (unsigned int)((tp & (RING - 1)) * 352) + mydst0,
                  myx + (size_t)tp * 11 + slot,
                  ldr && (tp <= mylast));
        CP_COMMIT();

        // ── chain(t), packed {A,B} ──
        ull acc2 = xd2;
        ffma2(acc2, whh2[0], h01.x);
        ffma2(acc2, whh2[1], h01.y);
        ffma2(acc2, whh2[2], h23.x);
        ffma2(acc2, whh2[3], h23.y);
        ffma2(acc2, whh2[4], h45.x);
        ffma2(acc2, whh2[5], h45.y);
        ffma2(acc2, whh2[6], h67.x);
        ffma2(acc2, whh2[7], h67.y);

        // a = al + be * rcp(1 + ex2(m * acc))
        const ull u2 = rcp_2(add2(one2, ex2_2(mul2(m2, acc2))));
        const ull a2 = fma2v(be2, u2, al2);

        // gather i/f/g/o (64-bit shfl = 2 SASS each, 8 total)
        const ull iv2 = __shfl_sync(0xffffffffu, a2, jl);
        const ull fv2 = __shfl_sync(0xffffffffu, a2, jl + 8);
        const ull gv2 = __shfl_sync(0xffffffffu, a2, jl + 16);
        const ull ov2 = __shfl_sync(0xffffffffu, a2, jl + 24);

        // c' = f*c + i*g ; h = o * tanh(c')
        c2 = fma2v(fv2, c2, mul2(iv2, gv2));
        const ull th2 = fma2v(neg2, rcp_2(add2(one2, ex2_2(mul2(K2, c2)))), one2);
        const ull hl2 = mul2(ov2, th2);

        // publish h (lanes 0-7; hl2 there IS {hA[j], hB[j]})
        if (lane < 8) {
            shh[lane] = hl2;
            F2U h; h.u = hl2;
            if (t == lastA) *outA = h.f.x;
            if (t == lastB) *outB = h.f.y;
        }

        // collapse next xd (off the critical chain)
        {
            F2U sA; sA.u = add2(a0A, a1A);
            F2U sB; sB.u = add2(a0B, a1B);
            xd2 = pack2(sA.f.x + sA.f.y, sB.f.x + sB.f.y);
        }
    }
}

// ─────────────────────────────────────────────────────────────────────────────
// Finalize: per-path fc dot -> smem; counts + block scan -> segment sums;
// shfl softmax. One 1024-thread block.
// ─────────────────────────────────────────────────────────────────────────────
__global__ void __launch_bounds__(NGROUPS)
finalize_kernel(const int* __restrict__ group_ids,
                const float* __restrict__ fc_W,
                const float* __restrict__ fc_b,
                float* __restrict__ out)
{
    __shared__ float sdot[NPATHS];
    __shared__ int   scnt[NGROUPS];
    __shared__ int   sstart[NGROUPS];
    __shared__ int   wsum[32];
    __shared__ float warpred[32];
    __shared__ float bc;

    const int tid = threadIdx.x;
    const int wid = tid >> 5;
    const int lid = tid & 31;

    float w[8];
    #pragma unroll
    for (int j = 0; j < 8; j++) w[j] = fc_W[j];

    scnt[tid] = 0;
    __syncthreads();

    #pragma unroll
    for (int r = 0; r < NPATHS / NGROUPS; r++) {
        const int i = tid + r * NGROUPS;
        const float4* hp = (const float4*)(g_hlast + i * H_DIM);
        float4 h0 = hp[0], h1 = hp[1];
        float s = h0.x * w[0];
        s = fmaf(h0.y, w[1], s);
        s = fmaf(h0.z, w[2], s);
        s = fmaf(h0.w, w[3], s);
        s = fmaf(h1.x, w[4], s);
        s = fmaf(h1.y, w[5], s);
        s = fmaf(h1.z, w[6], s);
        s = fmaf(h1.w, w[7], s);
        sdot[i] = s;
        atomicAdd(&scnt[group_ids[i]], 1);
    }
    __syncthreads();

    const int myc = scnt[tid];
    int inc = myc;
    #pragma unroll
    for (int d = 1; d < 32; d <<= 1) {
        int n = __shfl_up_sync(0xffffffffu, inc, d);
        if (lid >= d) inc += n;
    }
    if (lid == 31) wsum[wid] = inc;
    __syncthreads();
    if (wid == 0) {
        int v = wsum[lid];
        int iv = v;
        #pragma unroll
        for (int d = 1; d < 32; d <<= 1) {
            int n = __shfl_up_sync(0xffffffffu, iv, d);
            if (lid >= d) iv += n;
        }
        wsum[lid] = iv - v;
    }
    __syncthreads();
    sstart[tid] = inc - myc + wsum[wid];
    __syncthreads();

    float logit = fc_b[0];
    {
        const int s = sstart[tid];
        const int e = s + myc;
        for (int i = s; i < e; i++) logit += sdot[i];
    }

    float m = logit;
    #pragma unroll
    for (int off = 16; off > 0; off >>= 1) m = fmaxf(m, __shfl_xor_sync(0xffffffffu, m, off));
    if (lid == 0) warpred[wid] = m;
    __syncthreads();
    if (wid == 0) {
        float v = warpred[lid];
        #pragma unroll
        for (int off = 16; off > 0; off >>= 1) v = fmaxf(v, __shfl_xor_sync(0xffffffffu, v, off));
        if (lid == 0) bc = v;
    }
    __syncthreads();
    const float mx = bc;

    const float e = __expf(logit - mx);

    float s = e;
    #pragma unroll
    for (int off = 16; off > 0; off >>= 1) s += __shfl_xor_sync(0xffffffffu, s, off);
    __syncthreads();
    if (lid == 0) warpred[wid] = s;
    __syncthreads();
    if (wid == 0) {
        float v = warpred[lid];
        #pragma unroll
        for (int off = 16; off > 0; off >>= 1) v += __shfl_xor_sync(0xffffffffu, v, off);
        if (lid == 0) bc = v;
    }
    __syncthreads();

    out[tid] = e * fast_rcp(bc);
}

extern "C" void kernel_launch(void* const* d_in, const int* in_sizes, int n_in,
                              void* d_out, int out_size)
{
    const float* x      = (const float*)d_in[0];
    const float* W_ih   = (const float*)d_in[1];
    const float* W_hh   = (const float*)d_in[2];
    const float* b_ih   = (const float*)d_in[3];
    const float* b_hh   = (const float*)d_in[4];
    const float* fc_W   = (const float*)d_in[5];
    const float* fc_b   = (const float*)d_in[6];
    const int*   last_i = (const int*)d_in[7];
    const int*   gids   = (const int*)d_in[8];
    float*       out    = (float*)d_out;

    sort_kernel<<<1, 1024>>>(last_i);
    lstm_kernel<<<NPATHS / 2, 32>>>(x, W_ih, W_hh, b_ih, b_hh, last_i);
    finalize_kernel<<<1, NGROUPS>>>(gids, fc_W, fc_b, out);
}

// round 10
// speedup vs baseline: 1.7409x; 1.0927x over previous
#include <cuda_runtime.h>
#include <cstdint>

#define T_DIM 256
#define D_DIM 44
#define H_DIM 8
#define NPATHS 8192
#define NGROUPS 1024
#define RING 4

// scratch
__device__ float g_hlast[NPATHS * H_DIM];
__device__ int   g_order[NPATHS];

__device__ __forceinline__ float fast_rcp(float x) {
    float r; asm("rcp.approx.f32 %0, %1;" : "=f"(r) : "f"(x)); return r;
}
__device__ __forceinline__ float fast_tanh(float x) {
    float r; asm("tanh.approx.f32 %0, %1;" : "=f"(r) : "f"(x)); return r;
}

typedef unsigned long long ull;
union F2U { ull u; float2 f; };

__device__ __forceinline__ ull pack2(float a, float b) {
    F2U t; t.f.x = a; t.f.y = b; return t.u;
}
__device__ __forceinline__ void ffma2(ull& d, ull a, ull b) {
    asm("fma.rn.f32x2 %0, %1, %2, %0;" : "+l"(d) : "l"(a), "l"(b));
}
__device__ __forceinline__ ull fma2v(ull a, ull b, ull c) {
    ull r; asm("fma.rn.f32x2 %0, %1, %2, %3;" : "=l"(r) : "l"(a), "l"(b), "l"(c)); return r;
}
__device__ __forceinline__ ull mul2(ull a, ull b) {
    ull r; asm("mul.rn.f32x2 %0, %1, %2;" : "=l"(r) : "l"(a), "l"(b)); return r;
}
__device__ __forceinline__ ull add2(ull a, ull b) {
    ull r; asm("add.rn.f32x2 %0, %1, %2;" : "=l"(r) : "l"(a), "l"(b)); return r;
}
__device__ __forceinline__ ull tanh_2(ull v) {
    F2U t; t.u = v; t.f.x = fast_tanh(t.f.x); t.f.y = fast_tanh(t.f.y); return t.u;
}

__device__ __forceinline__ unsigned int smem_u32(const void* p) {
    return (unsigned int)__cvta_generic_to_shared(p);
}
__device__ __forceinline__ void cp16_pred(unsigned int dst, const void* src, bool pred) {
    asm volatile(
        "{ .reg .pred q; setp.ne.u32 q, %2, 0;"
        " @q cp.async.ca.shared.global [%0], [%1], 16; }"
        :: "r"(dst), "l"(src), "r"((int)pred));
}
#define CP_COMMIT() asm volatile("cp.async.commit_group;" ::: "memory")
#define CP_WAIT2()  asm volatile("cp.async.wait_group 2;" ::: "memory")

// ─────────────────────────────────────────────────────────────────────────────
// Counting sort by last_idx DESCENDING (parallel scan, int4-vectorized).
// ─────────────────────────────────────────────────────────────────────────────
__global__ void __launch_bounds__(1024)
sort_kernel(const int* __restrict__ last_idx)
{
    __shared__ int cnt[256];
    __shared__ int soff[256];
    __shared__ int wsum[8];
    __shared__ int wpre[8];
    const int tid = threadIdx.x;

    if (tid < 256) cnt[tid] = 0;
    __syncthreads();
    const int4* li4 = (const int4*)last_idx;
    #pragma unroll
    for (int i = tid; i < NPATHS / 4; i += 1024) {
        int4 v = li4[i];
        atomicAdd(&cnt[v.x], 1);
        atomicAdd(&cnt[v.y], 1);
        atomicAdd(&cnt[v.z], 1);
        atomicAdd(&cnt[v.w], 1);
    }
    __syncthreads();

    int v = 0;
    if (tid < 256) {
        const int r = tid;
        v = cnt[255 - r];
        #pragma unroll
        for (int d = 1; d < 32; d <<= 1) {
            int n = __shfl_up_sync(0xffffffffu, v, d);
            if ((r & 31) >= d) v += n;
        }
        if ((r & 31) == 31) wsum[r >> 5] = v;
    }
    __syncthreads();
    if (tid == 0) {
        int run = 0;
        #pragma unroll
        for (int w = 0; w < 8; w++) { wpre[w] = run; run += wsum[w]; }
    }
    __syncthreads();
    if (tid < 256) {
        const int r = tid;
        soff[255 - r] = v - cnt[255 - r] + wpre[r >> 5];
    }
    __syncthreads();
    if (tid < 256) cnt[tid] = 0;
    __syncthreads();

    #pragma unroll
    for (int i = tid; i < NPATHS / 4; i += 1024) {
        int4 L = li4[i];
        const int base = i * 4;
        g_order[soff[L.x] + atomicAdd(&cnt[L.x], 1)] = base + 0;
        g_order[soff[L.y] + atomicAdd(&cnt[L.y], 1)] = base + 1;
        g_order[soff[L.z] + atomicAdd(&cnt[L.z], 1)] = base + 2;
        g_order[soff[L.w] + atomicAdd(&cnt[L.w], 1)] = base + 3;
    }
}

// ─────────────────────────────────────────────────────────────────────────────
// LSTM: 1 warp/block, two length-matched paths packed {A,B} in f32x2.
// Activations via tanh.approx (MUFU): a = al + be*tanh(acc'), with the tanh
// input scale folded into the (register-resident) weights and bias.
// ─────────────────────────────────────────────────────────────────────────────
__global__ void __launch_bounds__(32, 18)
lstm_kernel(const float* __restrict__ x,
            const float* __restrict__ W_ih,
            const float* __restrict__ W_hh,
            const float* __restrict__ b_ih,
            const float* __restrict__ b_hh,
            const int* __restrict__ last_idx)
{
    __shared__ float4 sx[RING][2][11];        // x ring: [stage][side][11 float4]
    __shared__ __align__(16) ull shh[8];      // h packed {hA[j], hB[j]}

    const int lane = threadIdx.x;
    const int pA = g_order[2 * blockIdx.x];
    const int pB = g_order[2 * blockIdx.x + 1];

    // activation mapping: sigmoid(v) = 0.5 + 0.5*tanh(0.5*v); tanh(v) = tanh(v)
    // lanes 16-23 are the g gate (tanh); others sigmoid.
    const bool isg = (lane >= 16) && (lane < 24);
    const float m_s  = isg ? 1.0f : 0.5f;     // folded into weights/bias
    const float al_s = isg ? 0.0f : 0.5f;
    const float be_s = isg ? 1.0f : 0.5f;
    const ull al2 = pack2(al_s, al_s);
    const ull be2 = pack2(be_s, be_s);

    // packed, PRE-SCALED W_ih row for this lane's gate (REGISTERS)
    ull wihP[22];
    {
        const float2* wr = (const float2*)(W_ih + lane * 44);
        #pragma unroll
        for (int k2 = 0; k2 < 22; k2++) {
            float2 v = wr[k2];
            wihP[k2] = pack2(v.x * m_s, v.y * m_s);
        }
    }
    // W_hh row, dup-packed and pre-scaled
    ull whh2[8];
    {
        const float4* wr = (const float4*)(W_hh + lane * 8);
        float4 v0 = wr[0], v1 = wr[1];
        whh2[0]=pack2(v0.x*m_s,v0.x*m_s); whh2[1]=pack2(v0.y*m_s,v0.y*m_s);
        whh2[2]=pack2(v0.z*m_s,v0.z*m_s); whh2[3]=pack2(v0.w*m_s,v0.w*m_s);
        whh2[4]=pack2(v1.x*m_s,v1.x*m_s); whh2[5]=pack2(v1.y*m_s,v1.y*m_s);
        whh2[6]=pack2(v1.z*m_s,v1.z*m_s); whh2[7]=pack2(v1.w*m_s,v1.w*m_s);
    }
    const float bias = (b_ih[lane] + b_hh[lane]) * m_s;
    const ull biasPk = pack2(bias, 0.0f);

    const int lastA = last_idx[pA];
    const int lastB = last_idx[pB];
    const int tmax  = max(lastA, lastB);
    const int jl    = lane & 7;

    const float4* xrA = (const float4*)(x + (size_t)pA * T_DIM * D_DIM);
    const float4* xrB = (const float4*)(x + (size_t)pB * T_DIM * D_DIM);

    // loaders: lanes 0-10 -> side A, lanes 16-26 -> side B
    const int  side   = lane >> 4;
    const int  slot   = lane & 15;
    const bool ldr    = slot < 11;
    const float4* myx = side ? xrB : xrA;
    const int  mylast = side ? lastB : lastA;
    const unsigned int sbase  = smem_u32(&sx[0][0][0]);
    const unsigned int mydst0 = (unsigned int)((side * 11 + slot) * 16);

    // init h buffer
    if (lane < 8) shh[lane] = 0ull;

    // prologue: prefetch stages 0..3
    #pragma unroll
    for (int p = 0; p < RING; p++) {
        cp16_pred(sbase + (unsigned int)(p * 352) + mydst0,
                  myx + (size_t)p * 11 + slot,
                  ldr && (p <= mylast));
        CP_COMMIT();
    }

    ull c2 = 0ull;
    float* outA = g_hlast + pA * H_DIM + lane;        // valid when lane < 8
    float* outB = g_hlast + pB * H_DIM + lane;

    // initial xd(0)
    ull xd2;
    CP_WAIT2();
    __syncwarp();
    {
        const ulonglong2* xsA = (const ulonglong2*)&sx[0][0][0];
        const ulonglong2* xsB = (const ulonglong2*)&sx[0][1][0];
        ull a0A = biasPk, a1A = 0ull, a0B = biasPk, a1B = 0ull;
        #pragma unroll
        for (int k = 0; k < 11; k++) {
            ulonglong2 xvA = xsA[k];
            ulonglong2 xvB = xsB[k];
            ffma2(a0A, wihP[2*k],   xvA.x);
            ffma2(a1A, wihP[2*k+1], xvA.y);
            ffma2(a0B, wihP[2*k],   xvB.x);
            ffma2(a1B, wihP[2*k+1], xvB.y);
        }
        F2U sA; sA.u = add2(a0A, a1A);
        F2U sB; sB.u = add2(a0B, a1B);
        xd2 = pack2(sA.f.x + sA.f.y, sB.f.x + sB.f.y);
    }

    for (int t = 0; t <= tmax; t++) {
        CP_WAIT2();
        __syncwarp();   // x(t+1) visible warp-wide; also orders shh STS(t-1) -> LDS

        // load packed h(t-1): 4 warp-uniform LDS.128
        const ulonglong2* hp = (const ulonglong2*)shh;
        const ulonglong2 h01 = hp[0];
        const ulonglong2 h23 = hp[1];
        const ulonglong2 h45 = hp[2];
        const ulonglong2 h67 = hp[3];

        // ── independent: dot(t+1) for both paths (fills chain stall shadows) ──
        const int stg1 = (t + 1) & (RING - 1);
        const ulonglong2* xsA = (const ulonglong2*)&sx[stg1][0][0];
        const ulonglong2* xsB = (const ulonglong2*)&sx[stg1][1][0];
        ull a0A = biasPk, a1A = 0ull, a0B = biasPk, a1B = 0ull;
        #pragma unroll
        for (int k = 0; k < 11; k++) {
            ulonglong2 xvA = xsA[k];
            ulonglong2 xvB = xsB[k];
            ffma2(a0A, wihP[2*k],   xvA.x);
            ffma2(a1A, wihP[2*k+1], xvA.y);
            ffma2(a0B, wihP[2*k],   xvB.x);
            ffma2(a1B, wihP[2*k+1], xvB.y);
        }

        // prefetch stage t+4
        const int tp = t + RING;
        cp16_pred(sbase + (unsigned int)((tp & (RING - 1)) * 352) + mydst0,
                  myx + (size_t)tp * 11 + slot,
                  ldr && (tp <= mylast));
        CP_COMMIT();

        // ── chain(t), packed {A,B} ──
        ull acc2 = xd2;
        ffma2(acc2, whh2[0], h01.x);
        ffma2(acc2, whh2[1], h01.y);
        ffma2(acc2, whh2[2], h23.x);
        ffma2(acc2, whh2[3], h23.y);
        ffma2(acc2, whh2[4], h45.x);
        ffma2(acc2, whh2[5], h45.y);
        ffma2(acc2, whh2[6], h67.x);
        ffma2(acc2, whh2[7], h67.y);

        // a = al + be * tanh(acc)   (MUFU path; scale already folded in)
        const ull a2 = fma2v(be2, tanh_2(acc2), al2);

        // gather i/f/g/o (64-bit shfl)
        const ull iv2 = __shfl_sync(0xffffffffu, a2, jl);
        const ull fv2 = __shfl_sync(0xffffffffu, a2, jl + 8);
        const ull gv2 = __shfl_sync(0xffffffffu, a2, jl + 16);
        const ull ov2 = __shfl_sync(0xffffffffu, a2, jl + 24);

        // c' = f*c + i*g ; h = o * tanh(c')
        c2 = fma2v(fv2, c2, mul2(iv2, gv2));
        const ull hl2 = mul2(ov2, tanh_2(c2));

        // publish h (lanes 0-7; hl2 there IS {hA[j], hB[j]})
        if (lane < 8) {
            shh[lane] = hl2;
            F2U h; h.u = hl2;
            if (t == lastA) *outA = h.f.x;
            if (t == lastB) *outB = h.f.y;
        }

        // collapse next xd (off the critical chain)
        {
            F2U sA; sA.u = add2(a0A, a1A);
            F2U sB; sB.u = add2(a0B, a1B);
            xd2 = pack2(sA.f.x + sA.f.y, sB.f.x + sB.f.y);
        }
    }
}

// ─────────────────────────────────────────────────────────────────────────────
// Finalize: per-path fc dot -> smem; counts + block scan -> segment sums;
// shfl softmax. One 1024-thread block.
// ─────────────────────────────────────────────────────────────────────────────
__global__ void __launch_bounds__(NGROUPS)
finalize_kernel(const int* __restrict__ group_ids,
                const float* __restrict__ fc_W,
                const float* __restrict__ fc_b,
                float* __restrict__ out)
{
    __shared__ float sdot[NPATHS];
    __shared__ int   scnt[NGROUPS];
    __shared__ int   sstart[NGROUPS];
    __shared__ int   wsum[32];
    __shared__ float warpred[32];
    __shared__ float bc;

    const int tid = threadIdx.x;
    const int wid = tid >> 5;
    const int lid = tid & 31;

    float w[8];
    #pragma unroll
    for (int j = 0; j < 8; j++) w[j] = fc_W[j];

    scnt[tid] = 0;
    __syncthreads();

    #pragma unroll
    for (int r = 0; r < NPATHS / NGROUPS; r++) {
        const int i = tid + r * NGROUPS;
        const float4* hp = (const float4*)(g_hlast + i * H_DIM);
        float4 h0 = hp[0], h1 = hp[1];
        float s = h0.x * w[0];
        s = fmaf(h0.y, w[1], s);
        s = fmaf(h0.z, w[2], s);
        s = fmaf(h0.w, w[3], s);
        s = fmaf(h1.x, w[4], s);
        s = fmaf(h1.y, w[5], s);
        s = fmaf(h1.z, w[6], s);
        s = fmaf(h1.w, w[7], s);
        sdot[i] = s;
        atomicAdd(&scnt[group_ids[i]], 1);
    }
    __syncthreads();

    const int myc = scnt[tid];
    int inc = myc;
    #pragma unroll
    for (int d = 1; d < 32; d <<= 1) {
        int n = __shfl_up_sync(0xffffffffu, inc, d);
        if (lid >= d) inc += n;
    }
    if (lid == 31) wsum[wid] = inc;
    __syncthreads();
    if (wid == 0) {
        int v = wsum[lid];
        int iv = v;
        #pragma unroll
        for (int d = 1; d < 32; d <<= 1) {
            int n = __shfl_up_sync(0xffffffffu, iv, d);
            if (lid >= d) iv += n;
        }
        wsum[lid] = iv - v;
    }
    __syncthreads();
    sstart[tid] = inc - myc + wsum[wid];
    __syncthreads();

    float logit = fc_b[0];
    {
        const int s = sstart[tid];
        const int e = s + myc;
        for (int i = s; i < e; i++) logit += sdot[i];
    }

    float m = logit;
    #pragma unroll
    for (int off = 16; off > 0; off >>= 1) m = fmaxf(m, __shfl_xor_sync(0xffffffffu, m, off));
    if (lid == 0) warpred[wid] = m;
    __syncthreads();
    if (wid == 0) {
        float v = warpred[lid];
        #pragma unroll
        for (int off = 16; off > 0; off >>= 1) v = fmaxf(v, __shfl_xor_sync(0xffffffffu, v, off));
        if (lid == 0) bc = v;
    }
    __syncthreads();
    const float mx = bc;

    const float e = __expf(logit - mx);

    float s = e;
    #pragma unroll
    for (int off = 16; off > 0; off >>= 1) s += __shfl_xor_sync(0xffffffffu, s, off);
    __syncthreads();
    if (lid == 0) warpred[wid] = s;
    __syncthreads();
    if (wid == 0) {
        float v = warpred[lid];
        #pragma unroll
        for (int off = 16; off > 0; off >>= 1) v += __shfl_xor_sync(0xffffffffu, v, off);
        if (lid == 0) bc = v;
    }
    __syncthreads();

    out[tid] = e * fast_rcp(bc);
}

extern "C" void kernel_launch(void* const* d_in, const int* in_sizes, int n_in,
                              void* d_out, int out_size)
{
    const float* x      = (const float*)d_in[0];
    const float* W_ih   = (const float*)d_in[1];
    const float* W_hh   = (const float*)d_in[2];
    const float* b_ih   = (const float*)d_in[3];
    const float* b_hh   = (const float*)d_in[4];
    const float* fc_W   = (const float*)d_in[5];
    const float* fc_b   = (const float*)d_in[6];
    const int*   last_i = (const int*)d_in[7];
    const int*   gids   = (const int*)d_in[8];
    float*       out    = (float*)d_out;

    sort_kernel<<<1, 1024>>>(last_i);
    lstm_kernel<<<NPATHS / 2, 32>>>(x, W_ih, W_hh, b_ih, b_hh, last_i);
    finalize_kernel<<<1, NGROUPS>>>(gids, fc_W, fc_b, out);
}